// round 5
// baseline (speedup 1.0000x reference)
#include <cuda_runtime.h>
#include <math.h>
#include <float.h>

// Problem shapes (fixed by the reference)
#define B_   8
#define S_   160
#define V_   32000
#define M_   32       // B * REPEATS
#define SG_  64       // S_GEN
#define EM_  8        // E_MAX

// Scratch (device globals — no allocation allowed)
__device__ float g_lse_gen[M_ * SG_];          // LSE per gen row
__device__ float g_xg[M_ * SG_ * EM_];         // gen x gathered at entities, per (row, j)
__device__ float g_pred_kw[M_ * EM_];          // pred log-prob at entity (0 if invalid)

// ---------------------------------------------------------------------------
// Block-wide logsumexp combine: each thread holds (mx, s) meaning
// sum_i exp(x_i - mx). Returns mx_total + log(s_total) to all threads' lane 0
// consumer (value broadcast via shared).
// ---------------------------------------------------------------------------
__device__ __forceinline__ float block_lse(float mx, float s) {
    // warp combine
    #pragma unroll
    for (int o = 16; o > 0; o >>= 1) {
        float om = __shfl_xor_sync(0xffffffffu, mx, o);
        float os = __shfl_xor_sync(0xffffffffu, s,  o);
        float nm = fmaxf(mx, om);
        s  = s * __expf(mx - nm) + os * __expf(om - nm);
        mx = nm;
    }
    __shared__ float sm_m[16], sm_s[16];
    int w = threadIdx.x >> 5;
    int l = threadIdx.x & 31;
    int nw = (blockDim.x + 31) >> 5;
    if (l == 0) { sm_m[w] = mx; sm_s[w] = s; }
    __syncthreads();
    if (threadIdx.x == 0) {
        float fm = sm_m[0], fs = sm_s[0];
        for (int i = 1; i < nw; i++) {
            float om = sm_m[i], os = sm_s[i];
            float nm = fmaxf(fm, om);
            fs = fs * __expf(fm - nm) + os * __expf(om - nm);
            fm = nm;
        }
        sm_m[0] = fm + logf(fs);
    }
    __syncthreads();
    return sm_m[0];
}

// ---------------------------------------------------------------------------
// Streaming online-LSE over one vocab row (V_ floats, float4-vectorized).
// ---------------------------------------------------------------------------
__device__ __forceinline__ float row_lse(const float* __restrict__ row) {
    const float4* p4 = reinterpret_cast<const float4*>(row);
    float mx = -FLT_MAX;
    float s0 = 0.f, s1 = 0.f, s2 = 0.f, s3 = 0.f;
    #pragma unroll 2
    for (int i = threadIdx.x; i < V_ / 4; i += 512) {
        float4 v = __ldg(p4 + i);
        float mv = fmaxf(fmaxf(v.x, v.y), fmaxf(v.z, v.w));
        if (mv > mx) {              // rarely taken after warm-up
            float r = __expf(mx - mv);
            s0 *= r; s1 *= r; s2 *= r; s3 *= r;
            mx = mv;
        }
        s0 += __expf(v.x - mx);
        s1 += __expf(v.y - mx);
        s2 += __expf(v.z - mx);
        s3 += __expf(v.w - mx);
    }
    return block_lse(mx, (s0 + s1) + (s2 + s3));
}

// ---------------------------------------------------------------------------
// Kernel A: one block per (m, s) row of gen_cap_preds.
// Writes LSE and the 8 entity gathers (data is L1/L2-resident after stream).
// ---------------------------------------------------------------------------
__global__ __launch_bounds__(512) void k_gen_lse(const float* __restrict__ gen,
                                                 const int* __restrict__ entities) {
    int r = blockIdx.x;              // 0 .. M_*SG_-1
    int m = r >> 6;                  // row / SG_
    const float* row = gen + (size_t)r * V_;
    float lse = row_lse(row);
    if (threadIdx.x == 0) g_lse_gen[r] = lse;
    if (threadIdx.x < EM_) {
        int e = __ldg(entities + m * EM_ + threadIdx.x);
        g_xg[r * EM_ + threadIdx.x] = __ldg(row + e);
    }
}

// ---------------------------------------------------------------------------
// Kernel B: one block per (m, j). Only valid entries stream their preds row.
// ---------------------------------------------------------------------------
__global__ __launch_bounds__(512) void k_pred_lse(const float* __restrict__ preds,
                                                  const int* __restrict__ sample_index,
                                                  const int* __restrict__ entities,
                                                  const int* __restrict__ entity_counts,
                                                  const int* __restrict__ prefix_lens,
                                                  const int* __restrict__ prompt_length) {
    int idx = blockIdx.x;            // 0 .. M_*EM_-1
    int m = idx >> 3, j = idx & 7;
    int pos = __ldg(prompt_length) + __ldg(prefix_lens + m) - 1 + j;
    bool valid = (j < __ldg(entity_counts + m)) && (pos < S_);
    if (!valid) {
        if (threadIdx.x == 0) g_pred_kw[idx] = 0.f;
        return;
    }
    int posc = min(max(pos, 0), S_ - 1);
    int b = __ldg(sample_index + m);
    const float* row = preds + ((size_t)b * S_ + posc) * V_;
    float lse = row_lse(row);
    if (threadIdx.x == 0) {
        int e = __ldg(entities + idx);
        g_pred_kw[idx] = __ldg(row + e) - lse;
    }
}

// ---------------------------------------------------------------------------
// Kernel C: final scalar. One block of 256 threads, one thread per (m, j).
// ---------------------------------------------------------------------------
__global__ __launch_bounds__(256) void k_final(const int* __restrict__ entity_counts,
                                               const int* __restrict__ prefix_lens,
                                               const int* __restrict__ prompt_length,
                                               float* __restrict__ out) {
    __shared__ float shLSE[M_];
    int t = threadIdx.x;
    if (t < M_) {
        float s = 0.f;
        #pragma unroll 4
        for (int ss = 0; ss < SG_; ss++) s += g_lse_gen[t * SG_ + ss];
        shLSE[t] = s;
    }
    __syncthreads();

    int m = t >> 3, j = t & 7;
    int pos = __ldg(prompt_length) + __ldg(prefix_lens + m) - 1 + j;
    int cnt = __ldg(entity_counts + m);
    float term = 0.f;
    if ((j < cnt) && (pos < S_)) {
        float sx = 0.f;
        #pragma unroll 4
        for (int ss = 0; ss < SG_; ss++) sx += g_xg[(m * SG_ + ss) * EM_ + j];
        float gen_kw = (sx - shLSE[m]) * (1.f / (float)SG_);
        term = (g_pred_kw[t] - gen_kw) / (float)cnt;
    }

    // block reduce (256 threads)
    #pragma unroll
    for (int o = 16; o > 0; o >>= 1) term += __shfl_xor_sync(0xffffffffu, term, o);
    __shared__ float sw[8];
    if ((t & 31) == 0) sw[t >> 5] = term;
    __syncthreads();
    if (t == 0) {
        float s = 0.f;
        #pragma unroll
        for (int w = 0; w < 8; w++) s += sw[w];
        out[0] = -s / (float)M_;
    }
}

// ---------------------------------------------------------------------------
// Entry point. Input order per metadata:
//   0: preds          f32 [B, S, V]
//   1: gen_cap_preds  f32 [M, S_GEN, V]
//   2: sample_index   i32 [M]
//   3: entities       i32 [M, E_MAX]
//   4: entity_counts  i32 [M]
//   5: prefix_lens    i32 [M]
//   6: prompt_length  i32 [1]
// ---------------------------------------------------------------------------
extern "C" void kernel_launch(void* const* d_in, const int* in_sizes, int n_in,
                              void* d_out, int out_size) {
    const float* preds   = (const float*)d_in[0];
    const float* gen     = (const float*)d_in[1];
    const int* samp      = (const int*)d_in[2];
    const int* ents      = (const int*)d_in[3];
    const int* cnts      = (const int*)d_in[4];
    const int* pref      = (const int*)d_in[5];
    const int* plen      = (const int*)d_in[6];
    float* out           = (float*)d_out;

    k_gen_lse<<<M_ * SG_, 512>>>(gen, ents);
    k_pred_lse<<<M_ * EM_, 512>>>(preds, samp, ents, cnts, pref, plen);
    k_final<<<1, 256>>>(cnts, pref, plen, out);
}